// round 1
// baseline (speedup 1.0000x reference)
#include <cuda_runtime.h>
#include <cuda_bf16.h>

// Problem constants
#define BATCH   4
#define SEQ     6144
#define DIM     384
#define FCHUNK  3
#define NB      12      // BATCH*FCHUNK
#define LEN     2048    // SEQ/FCHUNK
#define DIN     192     // DIM/2
#define DSTATE  16
#define DTRANK  24
#define MTOT    (NB*LEN)    // 24576

// ---------------------------------------------------------------------------
// Scratch (static __device__ arrays; no allocation allowed)
// ---------------------------------------------------------------------------
__device__ float g_xp[MTOT * DIM];           // (12,2048,384) in_proj output
__device__ float g_xc[NB * DIN * LEN];       // (b,d,l) conv+silu output (= z = u)
__device__ float g_dt[NB * DTRANK * LEN];    // (b,r,l)
__device__ float g_Bm[NB * LEN * DSTATE];    // (b,l,n)
__device__ float g_Cm[NB * LEN * DSTATE];    // (b,l,n)
__device__ float g_delta[NB * DIN * LEN];    // (b,d,l)
__device__ float g_yf[NB * DIN * LEN];       // forward scan out (b,d,l)
__device__ float g_yb[NB * DIN * LEN];       // backward scan out (b,d,l)

// ---------------------------------------------------------------------------
// GEMM: C[M,384] = A[M,384] @ W[384,384]^T + bias
// MODE 0: A = x (row-major), C = g_xp
// MODE 1: A gathered from (yf+yb+2*D*xc | xc), C = d_out
// BM=BN=128, BK=16, 256 threads, 8x8 per thread
// ---------------------------------------------------------------------------
template <int MODE>
__global__ __launch_bounds__(256, 2)
void gemm_kernel(const float* __restrict__ A,
                 const float* __restrict__ W,
                 const float* __restrict__ bias,
                 const float* __restrict__ Dv,
                 float* __restrict__ C)
{
    constexpr int BM = 128, BN = 128, BK = 16;
    __shared__ float As[BK][BM + 4];
    __shared__ float Bs[BK][BN + 4];

    const int m0 = blockIdx.y * BM;
    const int n0 = blockIdx.x * BN;
    const int tid = threadIdx.x;
    const int trow = tid >> 4;   // 0..15
    const int tcol = tid & 15;   // 0..15

    float acc[8][8];
#pragma unroll
    for (int i = 0; i < 8; i++)
#pragma unroll
        for (int j = 0; j < 8; j++) acc[i][j] = 0.f;

    const int bb    = m0 >> 11;      // m0 / 2048 (tiles never straddle b)
    const int lbase = m0 & 2047;

    for (int k0 = 0; k0 < DIM; k0 += BK) {
        // ---- load W tile (row-major N x K) -> Bs[k][n]
#pragma unroll
        for (int it = 0; it < 2; it++) {
            int f = it * 256 + tid;
            int r = f >> 2;
            int kq = (f & 3) * 4;
            float4 v = *(const float4*)&W[(n0 + r) * DIM + k0 + kq];
            Bs[kq + 0][r] = v.x; Bs[kq + 1][r] = v.y;
            Bs[kq + 2][r] = v.z; Bs[kq + 3][r] = v.w;
        }
        // ---- load A tile -> As[k][m]
        if (MODE == 0) {
#pragma unroll
            for (int it = 0; it < 2; it++) {
                int f = it * 256 + tid;
                int r = f >> 2;
                int kq = (f & 3) * 4;
                float4 v = *(const float4*)&A[(m0 + r) * DIM + k0 + kq];
                As[kq + 0][r] = v.x; As[kq + 1][r] = v.y;
                As[kq + 2][r] = v.z; As[kq + 3][r] = v.w;
            }
        } else {
#pragma unroll
            for (int it = 0; it < 2; it++) {
                int f = it * 256 + tid;
                int kk = f >> 5;           // 0..15
                int mq = (f & 31) * 4;     // 0..124
                int kg = k0 + kk;
                float4 v;
                if (kg < DIN) {
                    int off = ((bb * DIN + kg) * LEN) + lbase + mq;
                    float4 yf4 = *(const float4*)&g_yf[off];
                    float4 yb4 = *(const float4*)&g_yb[off];
                    float4 xc4 = *(const float4*)&g_xc[off];
                    float dd = 2.f * Dv[kg];
                    v.x = yf4.x + yb4.x + dd * xc4.x;
                    v.y = yf4.y + yb4.y + dd * xc4.y;
                    v.z = yf4.z + yb4.z + dd * xc4.z;
                    v.w = yf4.w + yb4.w + dd * xc4.w;
                } else {
                    int off = ((bb * DIN + (kg - DIN)) * LEN) + lbase + mq;
                    v = *(const float4*)&g_xc[off];
                }
                *(float4*)&As[kk][mq] = v;
            }
        }
        __syncthreads();

#pragma unroll
        for (int kk = 0; kk < BK; kk++) {
            float a[8], bf[8];
            *(float4*)&a[0]  = *(const float4*)&As[kk][trow * 8];
            *(float4*)&a[4]  = *(const float4*)&As[kk][trow * 8 + 4];
            *(float4*)&bf[0] = *(const float4*)&Bs[kk][tcol * 8];
            *(float4*)&bf[4] = *(const float4*)&Bs[kk][tcol * 8 + 4];
#pragma unroll
            for (int i = 0; i < 8; i++)
#pragma unroll
                for (int j = 0; j < 8; j++)
                    acc[i][j] = fmaf(a[i], bf[j], acc[i][j]);
        }
        __syncthreads();
    }

    // epilogue
#pragma unroll
    for (int i = 0; i < 8; i++) {
        int row = m0 + trow * 8 + i;
#pragma unroll
        for (int j4 = 0; j4 < 2; j4++) {
            int col = n0 + tcol * 8 + j4 * 4;
            float4 o;
            o.x = acc[i][j4 * 4 + 0] + bias[col + 0];
            o.y = acc[i][j4 * 4 + 1] + bias[col + 1];
            o.z = acc[i][j4 * 4 + 2] + bias[col + 2];
            o.w = acc[i][j4 * 4 + 3] + bias[col + 3];
            *(float4*)&C[row * DIM + col] = o;
        }
    }
}

// ---------------------------------------------------------------------------
// Grouped conv (k=3, SAME, groups=192, 2 in-ch per group) + SiLU
// reads g_xp (b,l,c), writes g_xc (b,d,l)
// block (32,32): 32 l x 32 d tile
// ---------------------------------------------------------------------------
__global__ __launch_bounds__(1024)
void conv_silu_kernel(const float* __restrict__ conv_w,
                      const float* __restrict__ conv_b)
{
    __shared__ float s[34][65];
    const int b  = blockIdx.z;
    const int d0 = blockIdx.y * 32;
    const int l0 = blockIdx.x * 32;
    const int tid = threadIdx.y * 32 + threadIdx.x;

    for (int e = tid; e < 34 * 64; e += 1024) {
        int li = e >> 6;        // 0..33
        int ci = e & 63;        // 0..63
        int l = l0 - 1 + li;
        float v = 0.f;
        if (l >= 0 && l < LEN)
            v = g_xp[(b * LEN + l) * DIM + 2 * d0 + ci];
        s[li][ci] = v;
    }
    __syncthreads();

    const int tx = threadIdx.x, ty = threadIdx.y;
    const int d = d0 + ty;
    float acc = conv_b[d];
    const float* w = conv_w + d * 6;   // (d, i, j)
#pragma unroll
    for (int i = 0; i < 2; i++)
#pragma unroll
        for (int j = 0; j < 3; j++)
            acc = fmaf(s[tx + j][2 * ty + i], w[i * 3 + j], acc);
    // silu
    float y = acc / (1.f + __expf(-acc));
    g_xc[(b * DIN + d) * LEN + l0 + tx] = y;
}

// ---------------------------------------------------------------------------
// x_proj: x_dbl[b,r,l] = sum_d W[r,d] * xc[b,d,l], split into dt / B / C
// 128 threads, one l each; W cached in smem (43KB)
// ---------------------------------------------------------------------------
__global__ __launch_bounds__(128)
void xproj_kernel(const float* __restrict__ x_proj_w)
{
    __shared__ float sW[56 * DIN];
    const int b = blockIdx.y;
    const int l = blockIdx.x * 128 + threadIdx.x;

    for (int i = threadIdx.x; i < 56 * DIN; i += 128) sW[i] = x_proj_w[i];
    __syncthreads();

    float acc[56];
#pragma unroll
    for (int r = 0; r < 56; r++) acc[r] = 0.f;

    for (int d = 0; d < DIN; d++) {
        float v = g_xc[(b * DIN + d) * LEN + l];
#pragma unroll
        for (int r = 0; r < 56; r++)
            acc[r] = fmaf(sW[r * DIN + d], v, acc[r]);
    }
    // dt part (r < 24) -> g_dt (b,r,l)
#pragma unroll
    for (int r = 0; r < DTRANK; r++)
        g_dt[(b * DTRANK + r) * LEN + l] = acc[r];
    // B part -> (b,l,n)
    float4* Bp = (float4*)&g_Bm[(b * LEN + l) * DSTATE];
    float4* Cp = (float4*)&g_Cm[(b * LEN + l) * DSTATE];
#pragma unroll
    for (int q = 0; q < 4; q++) {
        float4 v;
        v.x = acc[DTRANK + q * 4 + 0];
        v.y = acc[DTRANK + q * 4 + 1];
        v.z = acc[DTRANK + q * 4 + 2];
        v.w = acc[DTRANK + q * 4 + 3];
        Bp[q] = v;
        float4 c;
        c.x = acc[DTRANK + DSTATE + q * 4 + 0];
        c.y = acc[DTRANK + DSTATE + q * 4 + 1];
        c.z = acc[DTRANK + DSTATE + q * 4 + 2];
        c.w = acc[DTRANK + DSTATE + q * 4 + 3];
        Cp[q] = c;
    }
}

// ---------------------------------------------------------------------------
// delta[b,d,l] = softplus(dt_proj_w[d,:] . dt[b,:,l] + dt_proj_b[d])
// ---------------------------------------------------------------------------
__global__ __launch_bounds__(128)
void delta_kernel(const float* __restrict__ dt_proj_w,
                  const float* __restrict__ dt_proj_b)
{
    __shared__ float sW[DIN * DTRANK];
    const int b = blockIdx.y;
    const int l = blockIdx.x * 128 + threadIdx.x;

    for (int i = threadIdx.x; i < DIN * DTRANK; i += 128) sW[i] = dt_proj_w[i];
    __syncthreads();

    float dt[DTRANK];
#pragma unroll
    for (int r = 0; r < DTRANK; r++)
        dt[r] = g_dt[(b * DTRANK + r) * LEN + l];

    for (int d = 0; d < DIN; d++) {
        float a = dt_proj_b[d];
#pragma unroll
        for (int r = 0; r < DTRANK; r++)
            a = fmaf(sW[d * DTRANK + r], dt[r], a);
        float sp = (a > 20.f) ? a : log1pf(__expf(a));
        g_delta[(b * DIN + d) * LEN + l] = sp;
    }
}

// ---------------------------------------------------------------------------
// Bidirectional selective scan.
// One warp per (b,d). Lanes 0-15: forward, state n = lane.
//                     Lanes 16-31: backward, state n = lane-16.
// h_{t} = exp(delta_t * A[n]) * h_{t-1} + delta_t * u_t * B[t,n]
// y_t = sum_n h_t[n] * C[t,n]
// ---------------------------------------------------------------------------
__global__ __launch_bounds__(128)
void scan_kernel(const float* __restrict__ A_log,
                 const float* __restrict__ Ab_log)
{
    const int warp_id = (blockIdx.x * blockDim.x + threadIdx.x) >> 5;
    const int lane = threadIdx.x & 31;
    if (warp_id >= NB * DIN) return;
    const int b = warp_id / DIN;
    const int d = warp_id % DIN;
    const int n = lane & 15;
    const bool bwd = lane >= 16;

    const float Aval = -__expf(bwd ? Ab_log[d * DSTATE + n]
                                   : A_log[d * DSTATE + n]);

    const float* dptr = g_delta + (b * DIN + d) * LEN;
    const float* uptr = g_xc    + (b * DIN + d) * LEN;
    const float* Bb   = g_Bm + b * LEN * DSTATE + n;
    const float* Cb   = g_Cm + b * LEN * DSTATE + n;
    float* yptr = (bwd ? g_yb : g_yf) + (b * DIN + d) * LEN;

    float h = 0.f;
#pragma unroll 2
    for (int t = 0; t < LEN; t++) {
        int l = bwd ? (LEN - 1 - t) : t;
        float delta = dptr[l];
        float u     = uptr[l];
        float Bn    = Bb[l * DSTATE];
        float Cn    = Cb[l * DSTATE];
        float dA = __expf(delta * Aval);
        h = fmaf(dA, h, delta * u * Bn);
        float p = h * Cn;
        p += __shfl_xor_sync(0xffffffffu, p, 1);
        p += __shfl_xor_sync(0xffffffffu, p, 2);
        p += __shfl_xor_sync(0xffffffffu, p, 4);
        p += __shfl_xor_sync(0xffffffffu, p, 8);
        if (n == 0) yptr[l] = p;
    }
}

// ---------------------------------------------------------------------------
// Launch
// ---------------------------------------------------------------------------
extern "C" void kernel_launch(void* const* d_in, const int* in_sizes, int n_in,
                              void* d_out, int out_size)
{
    (void)in_sizes; (void)n_in; (void)out_size;
    const float* x          = (const float*)d_in[0];
    const float* in_proj_w  = (const float*)d_in[1];
    const float* in_proj_b  = (const float*)d_in[2];
    const float* conv_w     = (const float*)d_in[3];
    const float* conv_b     = (const float*)d_in[4];
    const float* A_log      = (const float*)d_in[5];
    const float* Ab_log     = (const float*)d_in[6];
    const float* Dv         = (const float*)d_in[7];
    const float* x_proj_w   = (const float*)d_in[8];
    const float* dt_proj_w  = (const float*)d_in[9];
    const float* dt_proj_b  = (const float*)d_in[10];
    const float* out_proj_w = (const float*)d_in[11];
    const float* out_proj_b = (const float*)d_in[12];
    float* out = (float*)d_out;

    float* xp_ptr;
    cudaGetSymbolAddress((void**)&xp_ptr, g_xp);

    // 1. in_proj GEMM -> g_xp
    gemm_kernel<0><<<dim3(DIM / 128, MTOT / 128), 256>>>(
        x, in_proj_w, in_proj_b, nullptr, xp_ptr);

    // 2. conv + silu -> g_xc
    conv_silu_kernel<<<dim3(LEN / 32, DIN / 32, NB), dim3(32, 32)>>>(
        conv_w, conv_b);

    // 3. x_proj split -> g_dt, g_Bm, g_Cm
    xproj_kernel<<<dim3(LEN / 128, NB), 128>>>(x_proj_w);

    // 4. delta = softplus(dt_proj) -> g_delta
    delta_kernel<<<dim3(LEN / 128, NB), 128>>>(dt_proj_w, dt_proj_b);

    // 5. bidirectional scan -> g_yf, g_yb
    scan_kernel<<<(NB * DIN * 32 + 127) / 128, 128>>>(A_log, Ab_log);

    // 6. out_proj GEMM (gathered A) -> d_out
    gemm_kernel<1><<<dim3(DIM / 128, MTOT / 128), 256>>>(
        nullptr, out_proj_w, out_proj_b, Dv, out);
}

// round 3
// speedup vs baseline: 1.3227x; 1.3227x over previous
#include <cuda_runtime.h>
#include <cuda_bf16.h>
#include <cstdint>

// Problem constants
#define BATCH   4
#define SEQ     6144
#define DIM     384
#define FCHUNK  3
#define NB      12      // BATCH*FCHUNK
#define LEN     2048    // SEQ/FCHUNK
#define DIN     192     // DIM/2
#define DSTATE  16
#define DTRANK  24
#define MTOT    (NB*LEN)    // 24576

// ---------------------------------------------------------------------------
// Scratch (static __device__ arrays; no allocation allowed)
// ---------------------------------------------------------------------------
__device__ float g_xp[MTOT * DIM];           // (12,2048,384) in_proj output
__device__ float g_xc[NB * DIN * LEN];       // (b,d,l) conv+silu output (= z = u)
__device__ float g_dt[NB * DTRANK * LEN];    // (b,r,l)
__device__ float g_Bm[NB * LEN * DSTATE];    // (b,l,n)
__device__ float g_Cm[NB * LEN * DSTATE];    // (b,l,n)
__device__ float g_delta[NB * DIN * LEN];    // (b,d,l)
__device__ float g_yf[NB * DIN * LEN];       // fwd scan out; later ysum (b,d,l)
__device__ float g_yb[NB * DIN * LEN];       // bwd scan out (b,d,l)

// ---------------------------------------------------------------------------
// helpers
// ---------------------------------------------------------------------------
__device__ __forceinline__ uint32_t smem_u32(const void* p) {
    uint32_t a;
    asm("{ .reg .u64 t; cvta.to.shared.u64 t, %1; cvt.u32.u64 %0, t; }"
        : "=r"(a) : "l"(p));
    return a;
}
__device__ __forceinline__ uint32_t f2tf32(float x) {
    uint32_t r;
    asm("cvt.rna.tf32.f32 %0, %1;" : "=r"(r) : "f"(x));
    return r;
}
__device__ __forceinline__ void cp16(uint32_t dst, const void* src) {
    asm volatile("cp.async.ca.shared.global [%0], [%1], 16;"
                 :: "r"(dst), "l"(src) : "memory");
}
#define CP_COMMIT() asm volatile("cp.async.commit_group;" ::: "memory")
#define CP_WAIT1()  asm volatile("cp.async.wait_group 1;" ::: "memory")

__device__ __forceinline__ void mma_tf32(float* c, const uint32_t* a,
                                         const uint32_t* b) {
    asm volatile(
        "mma.sync.aligned.m16n8k8.row.col.f32.tf32.tf32.f32 "
        "{%0,%1,%2,%3}, {%4,%5,%6,%7}, {%8,%9}, {%0,%1,%2,%3};"
        : "+f"(c[0]), "+f"(c[1]), "+f"(c[2]), "+f"(c[3])
        : "r"(a[0]), "r"(a[1]), "r"(a[2]), "r"(a[3]), "r"(b[0]), "r"(b[1]));
}

// ---------------------------------------------------------------------------
// tf32 HMMA GEMM: C[M,384] = A[M,384] @ W[384,384]^T + bias
// MODE 0: A = plain row-major [m][k]           (in_proj: A = x)
// MODE 1: A read from (d,l)-layout sources:    (out_proj)
//           k < 192 -> g_yf (pre-fused ysum), k >= 192 -> g_xc
// Tile 128x128, BK=16, 256 threads (8 warps: 4 along M x 2 along N),
// warp tile 32x64, double-buffered cp.async.
// smem layouts:
//   MODE0: As[m][20]  (stride 20 -> conflict-free frag loads)
//   MODE1: As[k][136] (stride%32==8 -> conflict-free)
//   Bs[n][20] both modes (W is row-major [n][k])
// ---------------------------------------------------------------------------
#define AS_STRIDE0 20
#define AS_STRIDE1 136
#define BS_STRIDE  20
#define AS_FLOATS0 (128 * AS_STRIDE0)   // 2560
#define AS_FLOATS1 (16 * AS_STRIDE1)    // 2176
#define BS_FLOATS  (128 * BS_STRIDE)    // 2560

template <int MODE>
__global__ __launch_bounds__(256)
void gemm_tf32_kernel(const float* __restrict__ A,
                      const float* __restrict__ W,
                      const float* __restrict__ bias,
                      float* __restrict__ C)
{
    extern __shared__ float smf[];
    constexpr int AS_F = (MODE == 0) ? AS_FLOATS0 : AS_FLOATS1;
    float* AsBuf = smf;                 // 2 buffers of AS_F
    float* BsBuf = smf + 2 * AS_F;      // 2 buffers of BS_FLOATS

    const int tid  = threadIdx.x;
    const int wid  = tid >> 5;
    const int lane = tid & 31;
    const int g = lane >> 2;            // 0..7
    const int t = lane & 3;             // 0..3
    const int wm = wid >> 1;            // 0..3 (M direction)
    const int wn = wid & 1;             // 0..1 (N direction)

    const int m0 = blockIdx.y * 128;
    const int n0 = blockIdx.x * 128;
    const int bb = m0 >> 11;
    const int lbase = m0 & 2047;

    const uint32_t sAu = smem_u32(AsBuf);
    const uint32_t sBu = smem_u32(BsBuf);

    float acc[2][8][4];
#pragma unroll
    for (int mt = 0; mt < 2; mt++)
#pragma unroll
        for (int nt = 0; nt < 8; nt++)
#pragma unroll
            for (int q = 0; q < 4; q++) acc[mt][nt][q] = 0.f;

    // ---- tile loader (cp.async) ----
    auto load_tile = [&](int kt, int buf) {
        const int k0 = kt * 16;
        // Bs: 128 rows x 16 floats = 512 float4, 2 per thread
#pragma unroll
        for (int it = 0; it < 2; it++) {
            int idx = it * 256 + tid;
            int r = idx >> 2, c4 = idx & 3;
            uint32_t dst = sBu + (buf * BS_FLOATS + r * BS_STRIDE + c4 * 4) * 4;
            cp16(dst, &W[(n0 + r) * DIM + k0 + c4 * 4]);
        }
        if (MODE == 0) {
#pragma unroll
            for (int it = 0; it < 2; it++) {
                int idx = it * 256 + tid;
                int r = idx >> 2, c4 = idx & 3;
                uint32_t dst = sAu + (buf * AS_F + r * AS_STRIDE0 + c4 * 4) * 4;
                cp16(dst, &A[(m0 + r) * DIM + k0 + c4 * 4]);
            }
        } else {
            const float* srcb = (k0 < DIN)
                ? g_yf + ((size_t)(bb * DIN + k0) * LEN)
                : g_xc + ((size_t)(bb * DIN + (k0 - DIN)) * LEN);
#pragma unroll
            for (int it = 0; it < 2; it++) {
                int idx = it * 256 + tid;
                int kk = idx >> 5, m4 = idx & 31;
                uint32_t dst = sAu + (buf * AS_F + kk * AS_STRIDE1 + m4 * 4) * 4;
                cp16(dst, srcb + (size_t)kk * LEN + lbase + m4 * 4);
            }
        }
        CP_COMMIT();
    };

    load_tile(0, 0);

    for (int kt = 0; kt < 24; kt++) {
        const int buf = kt & 1;
        if (kt + 1 < 24) load_tile(kt + 1, buf ^ 1);
        else CP_COMMIT();   // empty group keeps wait bookkeeping uniform
        CP_WAIT1();
        __syncthreads();

        const float* As = AsBuf + buf * AS_F;
        const float* Bs = BsBuf + buf * BS_FLOATS;

#pragma unroll
        for (int s = 0; s < 2; s++) {
            // B fragments for all 8 n-tiles
            uint32_t bf[8][2];
#pragma unroll
            for (int nt = 0; nt < 8; nt++) {
                int n = wn * 64 + nt * 8 + g;
                bf[nt][0] = f2tf32(Bs[n * BS_STRIDE + s * 8 + t]);
                bf[nt][1] = f2tf32(Bs[n * BS_STRIDE + s * 8 + t + 4]);
            }
#pragma unroll
            for (int mt = 0; mt < 2; mt++) {
                int row = wm * 32 + mt * 16 + g;
                uint32_t af[4];
                if (MODE == 0) {
                    af[0] = f2tf32(As[row * AS_STRIDE0 + s * 8 + t]);
                    af[1] = f2tf32(As[(row + 8) * AS_STRIDE0 + s * 8 + t]);
                    af[2] = f2tf32(As[row * AS_STRIDE0 + s * 8 + t + 4]);
                    af[3] = f2tf32(As[(row + 8) * AS_STRIDE0 + s * 8 + t + 4]);
                } else {
                    af[0] = f2tf32(As[(s * 8 + t) * AS_STRIDE1 + row]);
                    af[1] = f2tf32(As[(s * 8 + t) * AS_STRIDE1 + row + 8]);
                    af[2] = f2tf32(As[(s * 8 + t + 4) * AS_STRIDE1 + row]);
                    af[3] = f2tf32(As[(s * 8 + t + 4) * AS_STRIDE1 + row + 8]);
                }
#pragma unroll
                for (int nt = 0; nt < 8; nt++)
                    mma_tf32(acc[mt][nt], af, bf[nt]);
            }
        }
        __syncthreads();
    }

    // ---- epilogue ----
#pragma unroll
    for (int mt = 0; mt < 2; mt++) {
        int row = m0 + wm * 32 + mt * 16 + g;
#pragma unroll
        for (int nt = 0; nt < 8; nt++) {
            int col = n0 + wn * 64 + nt * 8 + t * 2;
            float b0 = bias[col], b1 = bias[col + 1];
            float2 v0 = make_float2(acc[mt][nt][0] + b0, acc[mt][nt][1] + b1);
            float2 v1 = make_float2(acc[mt][nt][2] + b0, acc[mt][nt][3] + b1);
            *(float2*)&C[(size_t)row * DIM + col] = v0;
            *(float2*)&C[(size_t)(row + 8) * DIM + col] = v1;
        }
    }
}

// ---------------------------------------------------------------------------
// Grouped conv (k=3, SAME, groups=192, 2 in-ch per group) + SiLU
// ---------------------------------------------------------------------------
__global__ __launch_bounds__(1024)
void conv_silu_kernel(const float* __restrict__ conv_w,
                      const float* __restrict__ conv_b)
{
    __shared__ float s[34][65];
    const int b  = blockIdx.z;
    const int d0 = blockIdx.y * 32;
    const int l0 = blockIdx.x * 32;
    const int tid = threadIdx.y * 32 + threadIdx.x;

    for (int e = tid; e < 34 * 64; e += 1024) {
        int li = e >> 6;
        int ci = e & 63;
        int l = l0 - 1 + li;
        float v = 0.f;
        if (l >= 0 && l < LEN)
            v = g_xp[(b * LEN + l) * DIM + 2 * d0 + ci];
        s[li][ci] = v;
    }
    __syncthreads();

    const int tx = threadIdx.x, ty = threadIdx.y;
    const int d = d0 + ty;
    float acc = conv_b[d];
    const float* w = conv_w + d * 6;
#pragma unroll
    for (int i = 0; i < 2; i++)
#pragma unroll
        for (int j = 0; j < 3; j++)
            acc = fmaf(s[tx + j][2 * ty + i], w[i * 3 + j], acc);
    float y = acc / (1.f + __expf(-acc));
    g_xc[(b * DIN + d) * LEN + l0 + tx] = y;
}

// ---------------------------------------------------------------------------
// x_proj: x_dbl[b,r,l] = sum_d W[r,d]*xc[b,d,l]; r-chunked over blockIdx.z
// ---------------------------------------------------------------------------
__global__ __launch_bounds__(128)
void xproj_kernel(const float* __restrict__ x_proj_w)
{
    __shared__ float sW[14 * DIN];
    const int b = blockIdx.y;
    const int l = blockIdx.x * 128 + threadIdx.x;
    const int r0 = blockIdx.z * 14;

    for (int i = threadIdx.x; i < 14 * DIN; i += 128)
        sW[i] = x_proj_w[r0 * DIN + i];
    __syncthreads();

    float acc[14];
#pragma unroll
    for (int j = 0; j < 14; j++) acc[j] = 0.f;

    for (int d = 0; d < DIN; d++) {
        float v = g_xc[(b * DIN + d) * LEN + l];
#pragma unroll
        for (int j = 0; j < 14; j++)
            acc[j] = fmaf(sW[j * DIN + d], v, acc[j]);
    }
#pragma unroll
    for (int j = 0; j < 14; j++) {
        int r = r0 + j;
        if (r < DTRANK)
            g_dt[(b * DTRANK + r) * LEN + l] = acc[j];
        else if (r < DTRANK + DSTATE)
            g_Bm[(b * LEN + l) * DSTATE + (r - DTRANK)] = acc[j];
        else
            g_Cm[(b * LEN + l) * DSTATE + (r - DTRANK - DSTATE)] = acc[j];
    }
}

// ---------------------------------------------------------------------------
// delta[b,d,l] = softplus(dt_proj_w[d,:].dt[b,:,l] + dt_proj_b[d]); d-chunked
// ---------------------------------------------------------------------------
__global__ __launch_bounds__(128)
void delta_kernel(const float* __restrict__ dt_proj_w,
                  const float* __restrict__ dt_proj_b)
{
    __shared__ float sW[48 * DTRANK];
    const int b = blockIdx.y;
    const int l = blockIdx.x * 128 + threadIdx.x;
    const int d0 = blockIdx.z * 48;

    for (int i = threadIdx.x; i < 48 * DTRANK; i += 128)
        sW[i] = dt_proj_w[d0 * DTRANK + i];
    __syncthreads();

    float dt[DTRANK];
#pragma unroll
    for (int r = 0; r < DTRANK; r++)
        dt[r] = g_dt[(b * DTRANK + r) * LEN + l];

    for (int j = 0; j < 48; j++) {
        int d = d0 + j;
        float a = dt_proj_b[d];
#pragma unroll
        for (int r = 0; r < DTRANK; r++)
            a = fmaf(sW[j * DTRANK + r], dt[r], a);
        float sp = (a > 20.f) ? a : log1pf(__expf(a));
        g_delta[(b * DIN + d) * LEN + l] = sp;
    }
}

// ---------------------------------------------------------------------------
// Bidirectional selective scan (one warp per (b,d); 16 fwd + 16 bwd lanes)
// ---------------------------------------------------------------------------
__global__ __launch_bounds__(128)
void scan_kernel(const float* __restrict__ A_log,
                 const float* __restrict__ Ab_log)
{
    const int warp_id = (blockIdx.x * blockDim.x + threadIdx.x) >> 5;
    const int lane = threadIdx.x & 31;
    if (warp_id >= NB * DIN) return;
    const int b = warp_id / DIN;
    const int d = warp_id % DIN;
    const int n = lane & 15;
    const bool bwd = lane >= 16;

    const float Aval = -__expf(bwd ? Ab_log[d * DSTATE + n]
                                   : A_log[d * DSTATE + n]);

    const float* dptr = g_delta + (b * DIN + d) * LEN;
    const float* uptr = g_xc    + (b * DIN + d) * LEN;
    const float* Bb   = g_Bm + b * LEN * DSTATE + n;
    const float* Cb   = g_Cm + b * LEN * DSTATE + n;
    float* yptr = (bwd ? g_yb : g_yf) + (b * DIN + d) * LEN;

    float h = 0.f;
#pragma unroll 2
    for (int tt = 0; tt < LEN; tt++) {
        int l = bwd ? (LEN - 1 - tt) : tt;
        float delta = dptr[l];
        float u     = uptr[l];
        float Bn    = Bb[l * DSTATE];
        float Cn    = Cb[l * DSTATE];
        float dA = __expf(delta * Aval);
        h = fmaf(dA, h, delta * u * Bn);
        float p = h * Cn;
        p += __shfl_xor_sync(0xffffffffu, p, 1);
        p += __shfl_xor_sync(0xffffffffu, p, 2);
        p += __shfl_xor_sync(0xffffffffu, p, 4);
        p += __shfl_xor_sync(0xffffffffu, p, 8);
        if (n == 0) yptr[l] = p;
    }
}

// ---------------------------------------------------------------------------
// fuse: g_yf = g_yf + g_yb + 2*D[d]*g_xc   (elementwise, (b,d,l) layout)
// ---------------------------------------------------------------------------
__global__ __launch_bounds__(256)
void fuse_kernel(const float* __restrict__ Dv)
{
    const int total4 = NB * DIN * LEN / 4;
    for (int i4 = blockIdx.x * blockDim.x + threadIdx.x; i4 < total4;
         i4 += gridDim.x * blockDim.x) {
        int d = (i4 >> 9) % DIN;                // (i4*4 / LEN) % DIN
        float dd = 2.f * Dv[d];
        float4 yf4 = ((const float4*)g_yf)[i4];
        float4 yb4 = ((const float4*)g_yb)[i4];
        float4 xc4 = ((const float4*)g_xc)[i4];
        float4 o;
        o.x = yf4.x + yb4.x + dd * xc4.x;
        o.y = yf4.y + yb4.y + dd * xc4.y;
        o.z = yf4.z + yb4.z + dd * xc4.z;
        o.w = yf4.w + yb4.w + dd * xc4.w;
        ((float4*)g_yf)[i4] = o;
    }
}

// ---------------------------------------------------------------------------
// Launch
// ---------------------------------------------------------------------------
extern "C" void kernel_launch(void* const* d_in, const int* in_sizes, int n_in,
                              void* d_out, int out_size)
{
    (void)in_sizes; (void)n_in; (void)out_size;
    const float* x          = (const float*)d_in[0];
    const float* in_proj_w  = (const float*)d_in[1];
    const float* in_proj_b  = (const float*)d_in[2];
    const float* conv_w     = (const float*)d_in[3];
    const float* conv_b     = (const float*)d_in[4];
    const float* A_log      = (const float*)d_in[5];
    const float* Ab_log     = (const float*)d_in[6];
    const float* Dv         = (const float*)d_in[7];
    const float* x_proj_w   = (const float*)d_in[8];
    const float* dt_proj_w  = (const float*)d_in[9];
    const float* dt_proj_b  = (const float*)d_in[10];
    const float* out_proj_w = (const float*)d_in[11];
    const float* out_proj_b = (const float*)d_in[12];
    float* out = (float*)d_out;

    float* xp_ptr;
    cudaGetSymbolAddress((void**)&xp_ptr, g_xp);

    const int smem0 = (2 * AS_FLOATS0 + 2 * BS_FLOATS) * 4;   // 40960
    const int smem1 = (2 * AS_FLOATS1 + 2 * BS_FLOATS) * 4;   // 37888

    // 1. in_proj GEMM (tf32 HMMA) -> g_xp
    gemm_tf32_kernel<0><<<dim3(DIM / 128, MTOT / 128), 256, smem0>>>(
        x, in_proj_w, in_proj_b, xp_ptr);

    // 2. conv + silu -> g_xc
    conv_silu_kernel<<<dim3(LEN / 32, DIN / 32, NB), dim3(32, 32)>>>(
        conv_w, conv_b);

    // 3. x_proj split -> g_dt, g_Bm, g_Cm
    xproj_kernel<<<dim3(LEN / 128, NB, 4), 128>>>(x_proj_w);

    // 4. delta = softplus(dt_proj) -> g_delta
    delta_kernel<<<dim3(LEN / 128, NB, 4), 128>>>(dt_proj_w, dt_proj_b);

    // 5. bidirectional scan -> g_yf, g_yb
    scan_kernel<<<(NB * DIN * 32 + 127) / 128, 128>>>(A_log, Ab_log);

    // 6. fuse ysum = yf + yb + 2*D*xc -> g_yf
    fuse_kernel<<<1024, 256>>>(Dv);

    // 7. out_proj GEMM (tf32 HMMA, (d,l)-layout A) -> d_out
    gemm_tf32_kernel<1><<<dim3(DIM / 128, MTOT / 128), 256, smem1>>>(
        nullptr, out_proj_w, out_proj_b, out);
}

// round 4
// speedup vs baseline: 1.8981x; 1.4350x over previous
#include <cuda_runtime.h>
#include <cuda_bf16.h>
#include <cstdint>

// Problem constants
#define BATCH   4
#define SEQ     6144
#define DIM     384
#define FCHUNK  3
#define NB      12      // BATCH*FCHUNK
#define LEN     2048    // SEQ/FCHUNK
#define DIN     192     // DIM/2
#define DSTATE  16
#define DTRANK  24
#define MTOT    (NB*LEN)    // 24576

// ---------------------------------------------------------------------------
// Scratch (static __device__ arrays; no allocation allowed)
// ---------------------------------------------------------------------------
__device__ float g_xp[MTOT * DIM];           // (12,2048,384) in_proj output
__device__ float g_xc[NB * DIN * LEN];       // (b,d,l) conv+silu output (= z = u)
__device__ float g_dt[NB * DTRANK * LEN];    // (b,r,l)
__device__ float g_Bm[NB * LEN * DSTATE];    // (b,l,n)
__device__ float g_Cm[NB * LEN * DSTATE];    // (b,l,n)
__device__ float g_delta[NB * DIN * LEN];    // (b,d,l)
__device__ float g_yf[NB * DIN * LEN];       // fwd scan out; later ysum (b,d,l)
__device__ float g_yb[NB * DIN * LEN];       // bwd scan out (b,d,l)

// ---------------------------------------------------------------------------
// helpers
// ---------------------------------------------------------------------------
__device__ __forceinline__ uint32_t smem_u32(const void* p) {
    uint32_t a;
    asm("{ .reg .u64 t; cvta.to.shared.u64 t, %1; cvt.u32.u64 %0, t; }"
        : "=r"(a) : "l"(p));
    return a;
}
__device__ __forceinline__ uint32_t f2tf32(float x) {
    uint32_t r;
    asm("cvt.rna.tf32.f32 %0, %1;" : "=r"(r) : "f"(x));
    return r;
}
__device__ __forceinline__ void cp16(uint32_t dst, const void* src) {
    asm volatile("cp.async.ca.shared.global [%0], [%1], 16;"
                 :: "r"(dst), "l"(src) : "memory");
}
#define CP_COMMIT() asm volatile("cp.async.commit_group;" ::: "memory")
#define CP_WAIT1()  asm volatile("cp.async.wait_group 1;" ::: "memory")

__device__ __forceinline__ void mma_tf32(float* c, const uint32_t* a,
                                         const uint32_t* b) {
    asm volatile(
        "mma.sync.aligned.m16n8k8.row.col.f32.tf32.tf32.f32 "
        "{%0,%1,%2,%3}, {%4,%5,%6,%7}, {%8,%9}, {%0,%1,%2,%3};"
        : "+f"(c[0]), "+f"(c[1]), "+f"(c[2]), "+f"(c[3])
        : "r"(a[0]), "r"(a[1]), "r"(a[2]), "r"(a[3]), "r"(b[0]), "r"(b[1]));
}

// ---------------------------------------------------------------------------
// tf32 HMMA GEMM: C[M,384] = A[M,384] @ W[384,384]^T + bias
// MODE 0: A plain row-major [m][k]             (in_proj: A = x)
// MODE 1: A read from (d,l)-layout sources:    (out_proj)
//           k < 192 -> g_yf (pre-fused ysum), k >= 192 -> g_xc
// Tile 128x128, BK=32, 256 threads (8 warps: 4 M x 2 N), warp tile 32x64,
// 3-stage cp.async pipeline.
// smem: MODE0 As[m][36], MODE1 As[k][136]; Bs[n][36]. All conflict-free.
// ---------------------------------------------------------------------------
#define AS_STRIDE0 36
#define AS_STRIDE1 136
#define BS_STRIDE  36
#define AS_F0 (128 * AS_STRIDE0)   // 4608 floats / stage
#define AS_F1 (32 * AS_STRIDE1)    // 4352 floats / stage
#define BS_F  (128 * BS_STRIDE)    // 4608 floats / stage
#define GEMM_SMEM0 ((3 * (AS_F0 + BS_F)) * 4)   // 110592 B
#define GEMM_SMEM1 ((3 * (AS_F1 + BS_F)) * 4)   // 107520 B

template <int MODE>
__global__ __launch_bounds__(256, 2)
void gemm_tf32_kernel(const float* __restrict__ A,
                      const float* __restrict__ W,
                      const float* __restrict__ bias,
                      float* __restrict__ C)
{
    extern __shared__ float smf[];
    constexpr int AS_F = (MODE == 0) ? AS_F0 : AS_F1;
    float* AsBuf = smf;                 // 3 stages of AS_F
    float* BsBuf = smf + 3 * AS_F;      // 3 stages of BS_F

    const int tid  = threadIdx.x;
    const int wid  = tid >> 5;
    const int lane = tid & 31;
    const int g = lane >> 2;            // 0..7
    const int t = lane & 3;             // 0..3
    const int wm = wid >> 1;            // 0..3 (M)
    const int wn = wid & 1;             // 0..1 (N)

    const int m0 = blockIdx.y * 128;
    const int n0 = blockIdx.x * 128;
    const int bb = m0 >> 11;
    const int lbase = m0 & 2047;

    const uint32_t sAu = smem_u32(AsBuf);
    const uint32_t sBu = smem_u32(BsBuf);

    float acc[2][8][4];
#pragma unroll
    for (int mt = 0; mt < 2; mt++)
#pragma unroll
        for (int nt = 0; nt < 8; nt++)
#pragma unroll
            for (int q = 0; q < 4; q++) acc[mt][nt][q] = 0.f;

    auto load_tile = [&](int kt, int buf) {
        const int k0 = kt * 32;
        // Bs: 128 rows x 32 floats = 1024 float4, 4/thread
#pragma unroll
        for (int it = 0; it < 4; it++) {
            int idx = it * 256 + tid;
            int r = idx >> 3, c4 = idx & 7;
            uint32_t dst = sBu + (buf * BS_F + r * BS_STRIDE + c4 * 4) * 4;
            cp16(dst, &W[(n0 + r) * DIM + k0 + c4 * 4]);
        }
        if (MODE == 0) {
#pragma unroll
            for (int it = 0; it < 4; it++) {
                int idx = it * 256 + tid;
                int r = idx >> 3, c4 = idx & 7;
                uint32_t dst = sAu + (buf * AS_F + r * AS_STRIDE0 + c4 * 4) * 4;
                cp16(dst, &A[(m0 + r) * DIM + k0 + c4 * 4]);
            }
        } else {
            const float* srcb = (k0 < DIN)
                ? g_yf + ((size_t)(bb * DIN + k0) * LEN)
                : g_xc + ((size_t)(bb * DIN + (k0 - DIN)) * LEN);
#pragma unroll
            for (int it = 0; it < 4; it++) {
                int idx = it * 256 + tid;
                int kk = idx >> 5, m4 = idx & 31;
                uint32_t dst = sAu + (buf * AS_F + kk * AS_STRIDE1 + m4 * 4) * 4;
                cp16(dst, srcb + (size_t)kk * LEN + lbase + m4 * 4);
            }
        }
        CP_COMMIT();
    };

    load_tile(0, 0);
    load_tile(1, 1);

    for (int kt = 0; kt < 12; kt++) {
        CP_WAIT1();
        __syncthreads();

        if (kt + 2 < 12) load_tile(kt + 2, (kt + 2) % 3);
        else CP_COMMIT();   // uniform group bookkeeping

        const int buf = kt % 3;
        const float* As = AsBuf + buf * AS_F;
        const float* Bs = BsBuf + buf * BS_F;

#pragma unroll
        for (int s = 0; s < 4; s++) {
            uint32_t bf[8][2];
#pragma unroll
            for (int nt = 0; nt < 8; nt++) {
                int n = wn * 64 + nt * 8 + g;
                bf[nt][0] = f2tf32(Bs[n * BS_STRIDE + s * 8 + t]);
                bf[nt][1] = f2tf32(Bs[n * BS_STRIDE + s * 8 + t + 4]);
            }
#pragma unroll
            for (int mt = 0; mt < 2; mt++) {
                int row = wm * 32 + mt * 16 + g;
                uint32_t af[4];
                if (MODE == 0) {
                    af[0] = f2tf32(As[row * AS_STRIDE0 + s * 8 + t]);
                    af[1] = f2tf32(As[(row + 8) * AS_STRIDE0 + s * 8 + t]);
                    af[2] = f2tf32(As[row * AS_STRIDE0 + s * 8 + t + 4]);
                    af[3] = f2tf32(As[(row + 8) * AS_STRIDE0 + s * 8 + t + 4]);
                } else {
                    af[0] = f2tf32(As[(s * 8 + t) * AS_STRIDE1 + row]);
                    af[1] = f2tf32(As[(s * 8 + t) * AS_STRIDE1 + row + 8]);
                    af[2] = f2tf32(As[(s * 8 + t + 4) * AS_STRIDE1 + row]);
                    af[3] = f2tf32(As[(s * 8 + t + 4) * AS_STRIDE1 + row + 8]);
                }
#pragma unroll
                for (int nt = 0; nt < 8; nt++)
                    mma_tf32(acc[mt][nt], af, bf[nt]);
            }
        }
        __syncthreads();
    }

    // ---- epilogue ----
#pragma unroll
    for (int mt = 0; mt < 2; mt++) {
        int row = m0 + wm * 32 + mt * 16 + g;
#pragma unroll
        for (int nt = 0; nt < 8; nt++) {
            int col = n0 + wn * 64 + nt * 8 + t * 2;
            float b0 = bias[col], b1 = bias[col + 1];
            float2 v0 = make_float2(acc[mt][nt][0] + b0, acc[mt][nt][1] + b1);
            float2 v1 = make_float2(acc[mt][nt][2] + b0, acc[mt][nt][3] + b1);
            *(float2*)&C[(size_t)row * DIM + col] = v0;
            *(float2*)&C[(size_t)(row + 8) * DIM + col] = v1;
        }
    }
}

// ---------------------------------------------------------------------------
// Grouped conv (k=3, SAME, groups=192, 2 in-ch per group) + SiLU
// ---------------------------------------------------------------------------
__global__ __launch_bounds__(1024)
void conv_silu_kernel(const float* __restrict__ conv_w,
                      const float* __restrict__ conv_b)
{
    __shared__ float s[34][65];
    const int b  = blockIdx.z;
    const int d0 = blockIdx.y * 32;
    const int l0 = blockIdx.x * 32;
    const int tid = threadIdx.y * 32 + threadIdx.x;

    for (int e = tid; e < 34 * 64; e += 1024) {
        int li = e >> 6;
        int ci = e & 63;
        int l = l0 - 1 + li;
        float v = 0.f;
        if (l >= 0 && l < LEN)
            v = g_xp[(b * LEN + l) * DIM + 2 * d0 + ci];
        s[li][ci] = v;
    }
    __syncthreads();

    const int tx = threadIdx.x, ty = threadIdx.y;
    const int d = d0 + ty;
    float acc = conv_b[d];
    const float* w = conv_w + d * 6;
#pragma unroll
    for (int i = 0; i < 2; i++)
#pragma unroll
        for (int j = 0; j < 3; j++)
            acc = fmaf(s[tx + j][2 * ty + i], w[i * 3 + j], acc);
    float y = acc / (1.f + __expf(-acc));
    g_xc[(b * DIN + d) * LEN + l0 + tx] = y;
}

// ---------------------------------------------------------------------------
// x_proj: x_dbl[b,r,l] = sum_d W[r,d]*xc[b,d,l]; r-chunked over blockIdx.z
// ---------------------------------------------------------------------------
__global__ __launch_bounds__(128)
void xproj_kernel(const float* __restrict__ x_proj_w)
{
    __shared__ float sW[14 * DIN];
    const int b = blockIdx.y;
    const int l = blockIdx.x * 128 + threadIdx.x;
    const int r0 = blockIdx.z * 14;

    for (int i = threadIdx.x; i < 14 * DIN; i += 128)
        sW[i] = x_proj_w[r0 * DIN + i];
    __syncthreads();

    float acc[14];
#pragma unroll
    for (int j = 0; j < 14; j++) acc[j] = 0.f;

    for (int d = 0; d < DIN; d++) {
        float v = g_xc[(b * DIN + d) * LEN + l];
#pragma unroll
        for (int j = 0; j < 14; j++)
            acc[j] = fmaf(sW[j * DIN + d], v, acc[j]);
    }
#pragma unroll
    for (int j = 0; j < 14; j++) {
        int r = r0 + j;
        if (r < DTRANK)
            g_dt[(b * DTRANK + r) * LEN + l] = acc[j];
        else if (r < DTRANK + DSTATE)
            g_Bm[(b * LEN + l) * DSTATE + (r - DTRANK)] = acc[j];
        else
            g_Cm[(b * LEN + l) * DSTATE + (r - DTRANK - DSTATE)] = acc[j];
    }
}

// ---------------------------------------------------------------------------
// delta[b,d,l] = softplus(dt_proj_w[d,:].dt[b,:,l] + dt_proj_b[d]); d-chunk 24
// ---------------------------------------------------------------------------
__global__ __launch_bounds__(128)
void delta_kernel(const float* __restrict__ dt_proj_w,
                  const float* __restrict__ dt_proj_b)
{
    __shared__ float sW[24 * DTRANK];
    const int b = blockIdx.y;
    const int l = blockIdx.x * 128 + threadIdx.x;
    const int d0 = blockIdx.z * 24;

    for (int i = threadIdx.x; i < 24 * DTRANK; i += 128)
        sW[i] = dt_proj_w[d0 * DTRANK + i];
    __syncthreads();

    float dt[DTRANK];
#pragma unroll
    for (int r = 0; r < DTRANK; r++)
        dt[r] = g_dt[(b * DTRANK + r) * LEN + l];

#pragma unroll 4
    for (int j = 0; j < 24; j++) {
        int d = d0 + j;
        float a = dt_proj_b[d];
#pragma unroll
        for (int r = 0; r < DTRANK; r++)
            a = fmaf(sW[j * DTRANK + r], dt[r], a);
        float sp = (a > 20.f) ? a : log1pf(__expf(a));
        g_delta[(b * DIN + d) * LEN + l] = sp;
    }
}

// ---------------------------------------------------------------------------
// Bidirectional selective scan, 4-wide software pipelined.
// One warp per (b,d): lanes 0-15 fwd (state n=lane), 16-31 bwd (n=lane-16).
// ---------------------------------------------------------------------------
__global__ __launch_bounds__(256)
void scan_kernel(const float* __restrict__ A_log,
                 const float* __restrict__ Ab_log)
{
    const int warp_id = (blockIdx.x * blockDim.x + threadIdx.x) >> 5;
    const int lane = threadIdx.x & 31;
    if (warp_id >= NB * DIN) return;
    const int b = warp_id / DIN;
    const int d = warp_id % DIN;
    const int n = lane & 15;
    const bool bwd = lane >= 16;

    const float Aval = -__expf(bwd ? Ab_log[d * DSTATE + n]
                                   : A_log[d * DSTATE + n]);

    const float* dptr = g_delta + (size_t)(b * DIN + d) * LEN;
    const float* uptr = g_xc    + (size_t)(b * DIN + d) * LEN;
    const float* Bb   = g_Bm + (size_t)b * LEN * DSTATE + n;
    const float* Cb   = g_Cm + (size_t)b * LEN * DSTATE + n;
    float* yptr = (bwd ? g_yb : g_yf) + (size_t)(b * DIN + d) * LEN;

    float h = 0.f;
    for (int t0 = 0; t0 < LEN; t0 += 4) {
        float del[4], uu[4], Bn4[4], Cn4[4];
#pragma unroll
        for (int j = 0; j < 4; j++) {
            int l = bwd ? (LEN - 1 - (t0 + j)) : (t0 + j);
            del[j] = dptr[l];
            uu[j]  = uptr[l];
            Bn4[j] = Bb[(size_t)l * DSTATE];
            Cn4[j] = Cb[(size_t)l * DSTATE];
        }
        float dA[4];
#pragma unroll
        for (int j = 0; j < 4; j++) dA[j] = __expf(del[j] * Aval);

        float p[4];
#pragma unroll
        for (int j = 0; j < 4; j++) {
            h = fmaf(dA[j], h, del[j] * uu[j] * Bn4[j]);
            p[j] = h * Cn4[j];
        }
#pragma unroll
        for (int j = 0; j < 4; j++) {
            p[j] += __shfl_xor_sync(0xffffffffu, p[j], 1);
            p[j] += __shfl_xor_sync(0xffffffffu, p[j], 2);
            p[j] += __shfl_xor_sync(0xffffffffu, p[j], 4);
            p[j] += __shfl_xor_sync(0xffffffffu, p[j], 8);
        }
        if (n == 0) {
            if (!bwd) {
                float4 v = make_float4(p[0], p[1], p[2], p[3]);
                *(float4*)&yptr[t0] = v;
            } else {
                float4 v = make_float4(p[3], p[2], p[1], p[0]);
                *(float4*)&yptr[LEN - 4 - t0] = v;
            }
        }
    }
}

// ---------------------------------------------------------------------------
// fuse: g_yf = g_yf + g_yb + 2*D[d]*g_xc   (elementwise, (b,d,l) layout)
// ---------------------------------------------------------------------------
__global__ __launch_bounds__(256)
void fuse_kernel(const float* __restrict__ Dv)
{
    const int total4 = NB * DIN * LEN / 4;
    for (int i4 = blockIdx.x * blockDim.x + threadIdx.x; i4 < total4;
         i4 += gridDim.x * blockDim.x) {
        int d = (i4 >> 9) % DIN;
        float dd = 2.f * Dv[d];
        float4 yf4 = ((const float4*)g_yf)[i4];
        float4 yb4 = ((const float4*)g_yb)[i4];
        float4 xc4 = ((const float4*)g_xc)[i4];
        float4 o;
        o.x = yf4.x + yb4.x + dd * xc4.x;
        o.y = yf4.y + yb4.y + dd * xc4.y;
        o.z = yf4.z + yb4.z + dd * xc4.z;
        o.w = yf4.w + yb4.w + dd * xc4.w;
        ((float4*)g_yf)[i4] = o;
    }
}

// ---------------------------------------------------------------------------
// Launch
// ---------------------------------------------------------------------------
extern "C" void kernel_launch(void* const* d_in, const int* in_sizes, int n_in,
                              void* d_out, int out_size)
{
    (void)in_sizes; (void)n_in; (void)out_size;
    const float* x          = (const float*)d_in[0];
    const float* in_proj_w  = (const float*)d_in[1];
    const float* in_proj_b  = (const float*)d_in[2];
    const float* conv_w     = (const float*)d_in[3];
    const float* conv_b     = (const float*)d_in[4];
    const float* A_log      = (const float*)d_in[5];
    const float* Ab_log     = (const float*)d_in[6];
    const float* Dv         = (const float*)d_in[7];
    const float* x_proj_w   = (const float*)d_in[8];
    const float* dt_proj_w  = (const float*)d_in[9];
    const float* dt_proj_b  = (const float*)d_in[10];
    const float* out_proj_w = (const float*)d_in[11];
    const float* out_proj_b = (const float*)d_in[12];
    float* out = (float*)d_out;

    float* xp_ptr;
    cudaGetSymbolAddress((void**)&xp_ptr, g_xp);

    cudaFuncSetAttribute(gemm_tf32_kernel<0>,
                         cudaFuncAttributeMaxDynamicSharedMemorySize, GEMM_SMEM0);
    cudaFuncSetAttribute(gemm_tf32_kernel<1>,
                         cudaFuncAttributeMaxDynamicSharedMemorySize, GEMM_SMEM1);

    // 1. in_proj GEMM (tf32 HMMA) -> g_xp
    gemm_tf32_kernel<0><<<dim3(DIM / 128, MTOT / 128), 256, GEMM_SMEM0>>>(
        x, in_proj_w, in_proj_b, xp_ptr);

    // 2. conv + silu -> g_xc
    conv_silu_kernel<<<dim3(LEN / 32, DIN / 32, NB), dim3(32, 32)>>>(
        conv_w, conv_b);

    // 3. x_proj split -> g_dt, g_Bm, g_Cm
    xproj_kernel<<<dim3(LEN / 128, NB, 4), 128>>>(x_proj_w);

    // 4. delta = softplus(dt_proj) -> g_delta
    delta_kernel<<<dim3(LEN / 128, NB, 8), 128>>>(dt_proj_w, dt_proj_b);

    // 5. bidirectional scan -> g_yf, g_yb
    scan_kernel<<<(NB * DIN * 32 + 255) / 256, 256>>>(A_log, Ab_log);

    // 6. fuse ysum = yf + yb + 2*D*xc -> g_yf
    fuse_kernel<<<1024, 256>>>(Dv);

    // 7. out_proj GEMM (tf32 HMMA, (d,l)-layout A) -> d_out
    gemm_tf32_kernel<1><<<dim3(DIM / 128, MTOT / 128), 256, GEMM_SMEM1>>>(
        nullptr, out_proj_w, out_proj_b, out);
}